// round 11
// baseline (speedup 1.0000x reference)
#include <cuda_runtime.h>

#define B_   4
#define S_   2048
#define H_   16
#define HID_ 2048
#define DK_  128
#define DV_  128
#define P_   (B_*S_)   // 8192 positions

// scratch (allowed: __device__ globals)
__device__ float g_decay[P_*H_];
__device__ float g_beta [P_*H_];

// ============================================================
// Kernel 1: gating GEMM  raw = x @ [Wa;Wb]^T  + epilogue
// ============================================================
#define GT_POS 64
#define GT_K   32

__global__ __launch_bounds__(256) void gate_kernel(
    const float* __restrict__ x,
    const float* __restrict__ Wa, const float* __restrict__ Wb,
    const float* __restrict__ dt_bias, const float* __restrict__ A_log)
{
    __shared__ float xs[GT_POS][GT_K+1];
    __shared__ float ws[32][GT_K+1];
    int t  = threadIdx.x;
    int p0 = blockIdx.x * GT_POS;
    int tx = t & 7;
    int ty = t >> 3;
    float acc[2][4] = {};

    for (int kc = 0; kc < HID_; kc += GT_K) {
        #pragma unroll
        for (int i = 0; i < (GT_POS*GT_K)/256; ++i) {
            int e = i*256 + t; int r = e >> 5, c = e & 31;
            xs[r][c] = x[(size_t)(p0 + r)*HID_ + kc + c];
        }
        #pragma unroll
        for (int i = 0; i < (32*GT_K)/256; ++i) {
            int e = i*256 + t; int f = e >> 5, c = e & 31;
            const float* wrow = (f < 16) ? (Wa + f*HID_) : (Wb + (f-16)*HID_);
            ws[f][c] = wrow[kc + c];
        }
        __syncthreads();
        #pragma unroll
        for (int k = 0; k < GT_K; ++k) {
            float xv0 = xs[2*ty  ][k];
            float xv1 = xs[2*ty+1][k];
            #pragma unroll
            for (int j = 0; j < 4; ++j) {
                float wv = ws[4*tx+j][k];
                acc[0][j] = fmaf(xv0, wv, acc[0][j]);
                acc[1][j] = fmaf(xv1, wv, acc[1][j]);
            }
        }
        __syncthreads();
    }

    #pragma unroll
    for (int i = 0; i < 2; ++i) {
        int p = p0 + 2*ty + i;
        #pragma unroll
        for (int j = 0; j < 4; ++j) {
            int f = 4*tx + j;
            float r = acc[i][j];
            if (f < 16) {
                float z  = r + __ldg(dt_bias + f);
                float sp = fmaxf(z, 0.0f) + log1pf(expf(-fabsf(z)));
                g_decay[p*H_ + f] = expf(-expf(__ldg(A_log + f)) * sp);
            } else {
                g_beta[p*H_ + (f-16)] = r;
            }
        }
    }
}

// ============================================================
// Kernel 2: delta-rule scan. SMEM-broadcast k/q staging.
// CTA = 64 thr = 2 warps x 4 DV cols; grid = 64 bh x 16 = 1024
// (fine placement granularity: ~7 CTAs/SM, ~1.5% imbalance).
// Lane = (rg = lane>>2 owns rows 16rg..+15, co = lane&3 owns
// col colcta*8 + w*4 + co). State: 8 u64 (16 rows x 1 col).
// Fill: warp0 stages k, warp1 stages q; one LDG.128 + STS.128
// per warp per step with perm(c) = (c&3)*8 + (c>>2) so consumer
// LDS at index i*8+rg returns rows 16rg+4i..+3 (4-way broadcast,
// conflict-free). Main loop unrolled x4 -> slots are static.
// Per step:
//   p = redux8( k . S[:,col] )      (hadd + xor4,8,16)
//   d = (v - g*p) * beta
//   S = g*S + k (x) d
//   o = redux8( q . S_new[:,col] )  (off recurrence path)
// ============================================================
typedef unsigned long long u64;

__device__ __forceinline__ u64 fma2(u64 a, u64 b, u64 c) {
    u64 d; asm("fma.rn.f32x2 %0, %1, %2, %3;" : "=l"(d) : "l"(a), "l"(b), "l"(c));
    return d;
}
__device__ __forceinline__ u64 mul2(u64 a, u64 b) {
    u64 d; asm("mul.rn.f32x2 %0, %1, %2;" : "=l"(d) : "l"(a), "l"(b));
    return d;
}
__device__ __forceinline__ u64 pack2(float x, float y) {
    u64 d; asm("mov.b64 %0, {%1, %2};" : "=l"(d)
               : "r"(__float_as_uint(x)), "r"(__float_as_uint(y)));
    return d;
}
__device__ __forceinline__ float hadd2(u64 a) {
    unsigned lo, hi;
    asm("mov.b64 {%0, %1}, %2;" : "=r"(lo), "=r"(hi) : "l"(a));
    return __uint_as_float(lo) + __uint_as_float(hi);
}

struct PairPre {                 // prefetched v/g/beta for a step pair
    float v0, v1;
    float g0, b0, g1, b1;
};

__device__ __forceinline__ void load_pre(PairPre& p,
    const float* vb, const float* gb, const float* bb, int s, int col)
{
    if (s > S_ - 2) s = S_ - 2;
    p.v0 = __ldg(vb + (size_t)s     * (H_*DK_) + col);
    p.v1 = __ldg(vb + (size_t)(s+1) * (H_*DK_) + col);
    p.g0 = __ldg(gb + (size_t)s     * H_);
    p.b0 = __ldg(bb + (size_t)s     * H_);
    p.g1 = __ldg(gb + (size_t)(s+1) * H_);
    p.b1 = __ldg(bb + (size_t)(s+1) * H_);
}

__device__ __forceinline__ void do_step(const float4* sm, int slot,
                                        u64 st[8], float v, float g, float be,
                                        float* outp, int rg, int col)
{
    const unsigned FM = 0xffffffffu;
    const float4* kslot = sm + (slot*2 + 0)*32;
    const float4* qslot = sm + (slot*2 + 1)*32;
    u64 k2[8], q2[8];
    #pragma unroll
    for (int i = 0; i < 4; ++i) {
        ulonglong2 kk = *reinterpret_cast<const ulonglong2*>(kslot + i*8 + rg);
        k2[2*i] = kk.x; k2[2*i+1] = kk.y;
        ulonglong2 qq = *reinterpret_cast<const ulonglong2*>(qslot + i*8 + rg);
        q2[2*i] = qq.x; q2[2*i+1] = qq.y;
    }

    // ---- p = k . S[:,col] ----
    u64 pa = mul2(k2[0], st[0]);
    u64 pb = mul2(k2[1], st[1]);
    #pragma unroll
    for (int j = 2; j < 8; j += 2) {
        pa = fma2(k2[j],   st[j],   pa);
        pb = fma2(k2[j+1], st[j+1], pb);
    }
    float p = hadd2(pa) + hadd2(pb);
    p += __shfl_xor_sync(FM, p, 4);
    p += __shfl_xor_sync(FM, p, 8);
    p += __shfl_xor_sync(FM, p, 16);

    // ---- delta ----
    float d = fmaf(-g, p, v) * be;

    // ---- state update: S = g*S + k (x) d ----
    u64 gp = pack2(g, g), dp = pack2(d, d);
    #pragma unroll
    for (int j = 0; j < 8; ++j)
        st[j] = fma2(k2[j], dp, mul2(gp, st[j]));

    // ---- o = q . S_new[:,col] (off recurrence critical path) ----
    u64 oa = mul2(q2[0], st[0]);
    u64 ob = mul2(q2[1], st[1]);
    #pragma unroll
    for (int j = 2; j < 8; j += 2) {
        oa = fma2(q2[j],   st[j],   oa);
        ob = fma2(q2[j+1], st[j+1], ob);
    }
    float o = hadd2(oa) + hadd2(ob);
    o += __shfl_xor_sync(FM, o, 4);
    o += __shfl_xor_sync(FM, o, 8);
    o += __shfl_xor_sync(FM, o, 16);

    if (rg == 0)
        outp[col] = o;
}

__global__ void __launch_bounds__(64) scan_kernel(
    const float* __restrict__ q, const float* __restrict__ k,
    const float* __restrict__ v, float* __restrict__ out)
{
    // smem ring: 4 step slots x {k,q} x 32 float4
    __shared__ float4 sm[4*2*32];

    int bid    = blockIdx.x;         // 1024 CTAs
    int colcta = bid & 15;           // 8-col slice
    int bh     = bid >> 4;
    int b      = bh >> 4, h = bh & 15;
    int tid    = threadIdx.x;
    int w      = tid >> 5;           // warp 0..1
    int lane   = tid & 31;
    int rg     = lane >> 2;          // 0..7 row group (16 rows)
    int co     = lane & 3;           // col owner
    int col    = colcta*8 + w*4 + co;

    size_t base = ((size_t)b * S_ * H_ + h) * DK_;
    const float* kb = k + base;
    const float* qb = q + base;
    const float* vb = v + base;
    float*       ob = out + base;
    const float* gb = g_decay + (size_t)b * S_ * H_ + h;
    const float* bb = g_beta  + (size_t)b * S_ * H_ + h;

    // fill params: warp0 stages k, warp1 stages q
    int perm = ((lane & 3) << 3) | (lane >> 2);
    const float* fsrc = w ? qb : kb;
    float4* fdst_base = sm;          // + (slot*2 + w)*32 + perm

    // ---- pre-fill slots 0..3 = steps 0..3 ----
    #pragma unroll
    for (int fs = 0; fs < 4; ++fs) {
        float4 val = __ldg((const float4*)(fsrc + (size_t)fs*(H_*DK_)) + lane);
        fdst_base[(fs*2 + w)*32 + perm] = val;
    }
    __syncthreads();

    u64 st[8];
    #pragma unroll
    for (int j = 0; j < 8; ++j) st[j] = 0ull;

    PairPre Pc, Pd;
    load_pre(Pc, vb, gb, bb, 0, col);

    for (int s = 0; s < S_; s += 4) {
        load_pre(Pd, vb, gb, bb, s + 2, col);

        do_step(sm, 0, st, Pc.v0, Pc.g0, Pc.b0, ob + (size_t)s    *(H_*DV_), rg, col);
        do_step(sm, 1, st, Pc.v1, Pc.g1, Pc.b1, ob + (size_t)(s+1)*(H_*DV_), rg, col);

        __syncthreads();   // slots 0,1 consumed by all warps

        // fill slots 0,1 <- steps s+4, s+5
        {
            int f0 = (s + 4 < S_) ? s + 4 : S_ - 1;
            int f1 = (s + 5 < S_) ? s + 5 : S_ - 1;
            float4 v0 = __ldg((const float4*)(fsrc + (size_t)f0*(H_*DK_)) + lane);
            float4 v1 = __ldg((const float4*)(fsrc + (size_t)f1*(H_*DK_)) + lane);
            fdst_base[(0*2 + w)*32 + perm] = v0;
            fdst_base[(1*2 + w)*32 + perm] = v1;
        }
        load_pre(Pc, vb, gb, bb, s + 4, col);   // for next iteration

        do_step(sm, 2, st, Pd.v0, Pd.g0, Pd.b0, ob + (size_t)(s+2)*(H_*DV_), rg, col);
        do_step(sm, 3, st, Pd.v1, Pd.g1, Pd.b1, ob + (size_t)(s+3)*(H_*DV_), rg, col);

        __syncthreads();   // slots 2,3 consumed

        // fill slots 2,3 <- steps s+6, s+7 (consumed after next iter's 1st barrier)
        {
            int f2 = (s + 6 < S_) ? s + 6 : S_ - 1;
            int f3 = (s + 7 < S_) ? s + 7 : S_ - 1;
            float4 v2 = __ldg((const float4*)(fsrc + (size_t)f2*(H_*DK_)) + lane);
            float4 v3 = __ldg((const float4*)(fsrc + (size_t)f3*(H_*DK_)) + lane);
            fdst_base[(2*2 + w)*32 + perm] = v2;
            fdst_base[(3*2 + w)*32 + perm] = v3;
        }
    }
}

// ============================================================
extern "C" void kernel_launch(void* const* d_in, const int* in_sizes, int n_in,
                              void* d_out, int out_size)
{
    (void)in_sizes; (void)n_in; (void)out_size;
    const float* x   = (const float*)d_in[0];
    const float* q   = (const float*)d_in[1];
    const float* k   = (const float*)d_in[2];
    const float* v   = (const float*)d_in[3];
    const float* Wa  = (const float*)d_in[4];
    const float* Wb  = (const float*)d_in[5];
    const float* dtb = (const float*)d_in[6];
    const float* Al  = (const float*)d_in[7];
    float* out = (float*)d_out;

    gate_kernel<<<P_/GT_POS, 256>>>(x, Wa, Wb, dtb, Al);
    scan_kernel<<<B_*H_*16, 64>>>(q, k, v, out);
}

// round 12
// speedup vs baseline: 1.3984x; 1.3984x over previous
#include <cuda_runtime.h>

#define B_   4
#define S_   2048
#define H_   16
#define HID_ 2048
#define DK_  128
#define DV_  128
#define P_   (B_*S_)   // 8192 positions

// scratch (allowed: __device__ globals)
__device__ float g_decay[P_*H_];
__device__ float g_beta [P_*H_];

// ============================================================
// Kernel 1: gating GEMM  raw = x @ [Wa;Wb]^T  + epilogue
// ============================================================
#define GT_POS 64
#define GT_K   32

__global__ __launch_bounds__(256) void gate_kernel(
    const float* __restrict__ x,
    const float* __restrict__ Wa, const float* __restrict__ Wb,
    const float* __restrict__ dt_bias, const float* __restrict__ A_log)
{
    __shared__ float xs[GT_POS][GT_K+1];
    __shared__ float ws[32][GT_K+1];
    int t  = threadIdx.x;
    int p0 = blockIdx.x * GT_POS;
    int tx = t & 7;
    int ty = t >> 3;
    float acc[2][4] = {};

    for (int kc = 0; kc < HID_; kc += GT_K) {
        #pragma unroll
        for (int i = 0; i < (GT_POS*GT_K)/256; ++i) {
            int e = i*256 + t; int r = e >> 5, c = e & 31;
            xs[r][c] = x[(size_t)(p0 + r)*HID_ + kc + c];
        }
        #pragma unroll
        for (int i = 0; i < (32*GT_K)/256; ++i) {
            int e = i*256 + t; int f = e >> 5, c = e & 31;
            const float* wrow = (f < 16) ? (Wa + f*HID_) : (Wb + (f-16)*HID_);
            ws[f][c] = wrow[kc + c];
        }
        __syncthreads();
        #pragma unroll
        for (int k = 0; k < GT_K; ++k) {
            float xv0 = xs[2*ty  ][k];
            float xv1 = xs[2*ty+1][k];
            #pragma unroll
            for (int j = 0; j < 4; ++j) {
                float wv = ws[4*tx+j][k];
                acc[0][j] = fmaf(xv0, wv, acc[0][j]);
                acc[1][j] = fmaf(xv1, wv, acc[1][j]);
            }
        }
        __syncthreads();
    }

    #pragma unroll
    for (int i = 0; i < 2; ++i) {
        int p = p0 + 2*ty + i;
        #pragma unroll
        for (int j = 0; j < 4; ++j) {
            int f = 4*tx + j;
            float r = acc[i][j];
            if (f < 16) {
                float z  = r + __ldg(dt_bias + f);
                float sp = fmaxf(z, 0.0f) + log1pf(expf(-fabsf(z)));
                g_decay[p*H_ + f] = expf(-expf(__ldg(A_log + f)) * sp);
            } else {
                g_beta[p*H_ + (f-16)] = r;
            }
        }
    }
}

// ============================================================
// Kernel 2: delta-rule scan. R10 shape (256 CTAs x 256 thr, the
// proven fill machinery) + unrolled x8 main loop with an 8-slot
// static smem ring (literal slot indices -> no slot ALU) and only
// 2 barriers per 8 steps.
// CTA = 256 thr = 8 warps; warp w owns 4 DV cols; grid = 64 bh x
// 4 colcta. Lane = (rg = lane>>2 owns rows 16rg..+15, co = lane&3
// owns col). State: 8 u64 (16 rows x 1 col).
// Fill: thread (vecsel = tid>>5, c = lane) stages step s+vecsel/2
// of k (vecsel even) or q (vecsel odd) with perm(c)=(c&3)*8+(c>>2);
// consumer LDS at i*8+rg returns rows 16rg+4i..+3 (4-way
// broadcast, conflict-free).
// Per step:
//   p = redux8( k . S[:,col] )      (hadd + xor4,8,16)
//   d = (v - g*p) * beta
//   S = g*S + k (x) d
//   o = redux8( q . S_new[:,col] )  (off recurrence path)
// ============================================================
typedef unsigned long long u64;

__device__ __forceinline__ u64 fma2(u64 a, u64 b, u64 c) {
    u64 d; asm("fma.rn.f32x2 %0, %1, %2, %3;" : "=l"(d) : "l"(a), "l"(b), "l"(c));
    return d;
}
__device__ __forceinline__ u64 mul2(u64 a, u64 b) {
    u64 d; asm("mul.rn.f32x2 %0, %1, %2;" : "=l"(d) : "l"(a), "l"(b));
    return d;
}
__device__ __forceinline__ u64 pack2(float x, float y) {
    u64 d; asm("mov.b64 %0, {%1, %2};" : "=l"(d)
               : "r"(__float_as_uint(x)), "r"(__float_as_uint(y)));
    return d;
}
__device__ __forceinline__ float hadd2(u64 a) {
    unsigned lo, hi;
    asm("mov.b64 {%0, %1}, %2;" : "=r"(lo), "=r"(hi) : "l"(a));
    return __uint_as_float(lo) + __uint_as_float(hi);
}

struct QuadPre {                 // prefetched v/g/beta for 4 steps
    float v[4], g[4], b[4];
};

__device__ __forceinline__ void load_quad(QuadPre& p,
    const float* vb, const float* gb, const float* bb, int s, int col)
{
    #pragma unroll
    for (int i = 0; i < 4; ++i) {
        int si = s + i; if (si > S_ - 1) si = S_ - 1;
        p.v[i] = __ldg(vb + (size_t)si * (H_*DK_) + col);
        p.g[i] = __ldg(gb + (size_t)si * H_);
        p.b[i] = __ldg(bb + (size_t)si * H_);
    }
}

__device__ __forceinline__ void do_step(const float4* sm, int slot,
                                        u64 st[8], float v, float g, float be,
                                        float* outp, int rg, int col)
{
    const unsigned FM = 0xffffffffu;
    const float4* kslot = sm + (slot*2 + 0)*32;
    const float4* qslot = sm + (slot*2 + 1)*32;
    u64 k2[8], q2[8];
    #pragma unroll
    for (int i = 0; i < 4; ++i) {
        ulonglong2 kk = *reinterpret_cast<const ulonglong2*>(kslot + i*8 + rg);
        k2[2*i] = kk.x; k2[2*i+1] = kk.y;
        ulonglong2 qq = *reinterpret_cast<const ulonglong2*>(qslot + i*8 + rg);
        q2[2*i] = qq.x; q2[2*i+1] = qq.y;
    }

    // ---- p = k . S[:,col] ----
    u64 pa = mul2(k2[0], st[0]);
    u64 pb = mul2(k2[1], st[1]);
    #pragma unroll
    for (int j = 2; j < 8; j += 2) {
        pa = fma2(k2[j],   st[j],   pa);
        pb = fma2(k2[j+1], st[j+1], pb);
    }
    float p = hadd2(pa) + hadd2(pb);
    p += __shfl_xor_sync(FM, p, 4);
    p += __shfl_xor_sync(FM, p, 8);
    p += __shfl_xor_sync(FM, p, 16);

    // ---- delta ----
    float d = fmaf(-g, p, v) * be;

    // ---- state update: S = g*S + k (x) d ----
    u64 gp = pack2(g, g), dp = pack2(d, d);
    #pragma unroll
    for (int j = 0; j < 8; ++j)
        st[j] = fma2(k2[j], dp, mul2(gp, st[j]));

    // ---- o = q . S_new[:,col] (off recurrence critical path) ----
    u64 oa = mul2(q2[0], st[0]);
    u64 ob = mul2(q2[1], st[1]);
    #pragma unroll
    for (int j = 2; j < 8; j += 2) {
        oa = fma2(q2[j],   st[j],   oa);
        ob = fma2(q2[j+1], st[j+1], ob);
    }
    float o = hadd2(oa) + hadd2(ob);
    o += __shfl_xor_sync(FM, o, 4);
    o += __shfl_xor_sync(FM, o, 8);
    o += __shfl_xor_sync(FM, o, 16);

    if (rg == 0)
        outp[col] = o;
}

__global__ void __launch_bounds__(256, 2) scan_kernel(
    const float* __restrict__ q, const float* __restrict__ k,
    const float* __restrict__ v, float* __restrict__ out)
{
    // smem ring: 8 step slots x {k,q} x 32 float4 (8 KB)
    __shared__ float4 sm[8*2*32];

    int bid    = blockIdx.x;         // 256 CTAs
    int colcta = bid & 3;            // 32-col slice
    int bh     = bid >> 2;
    int b      = bh >> 4, h = bh & 15;
    int tid    = threadIdx.x;
    int w      = tid >> 5;           // warp 0..7
    int lane   = tid & 31;
    int rg     = lane >> 2;          // 0..7 row group (16 rows)
    int co     = lane & 3;           // col owner
    int col    = colcta*32 + w*4 + co;

    size_t base = ((size_t)b * S_ * H_ + h) * DK_;
    const float* kb = k + base;
    const float* qb = q + base;
    const float* vb = v + base;
    float*       ob = out + base;
    const float* gb = g_decay + (size_t)b * S_ * H_ + h;
    const float* bb = g_beta  + (size_t)b * S_ * H_ + h;

    // fill params: thread (vecsel = tid>>5, c = lane)
    int vecsel   = tid >> 5;         // (stepoff = vecsel>>1, kq = vecsel&1)
    int kq       = vecsel & 1;
    int fstep    = vecsel >> 1;      // 0..3
    int c        = lane;
    int perm     = ((c & 3) << 3) | (c >> 2);
    const float* fsrc = kq ? qb : kb;

    // ---- pre-fill slots 0..7 = steps 0..7 ----
    #pragma unroll
    for (int half = 0; half < 2; ++half) {
        int fs = half*4 + fstep;
        float4 val = __ldg((const float4*)(fsrc + (size_t)fs*(H_*DK_)) + c);
        sm[(fs*2 + kq)*32 + perm] = val;
    }
    __syncthreads();

    u64 st[8];
    #pragma unroll
    for (int j = 0; j < 8; ++j) st[j] = 0ull;

    QuadPre P0, P1;
    load_quad(P0, vb, gb, bb, 0, col);

    for (int s = 0; s < S_; s += 8) {
        load_quad(P1, vb, gb, bb, s + 4, col);

        // ---- consume slots 0..3 (steps s..s+3) ----
        do_step(sm, 0, st, P0.v[0], P0.g[0], P0.b[0], ob + (size_t)(s  )*(H_*DV_), rg, col);
        do_step(sm, 1, st, P0.v[1], P0.g[1], P0.b[1], ob + (size_t)(s+1)*(H_*DV_), rg, col);
        do_step(sm, 2, st, P0.v[2], P0.g[2], P0.b[2], ob + (size_t)(s+2)*(H_*DV_), rg, col);
        do_step(sm, 3, st, P0.v[3], P0.g[3], P0.b[3], ob + (size_t)(s+3)*(H_*DV_), rg, col);

        __syncthreads();   // slots 0..3 consumed by all warps

        // fill slots 0..3 <- steps s+8..s+11
        {
            int fs = s + 8 + fstep;
            if (fs > S_ - 1) fs = S_ - 1;
            float4 val = __ldg((const float4*)(fsrc + (size_t)fs*(H_*DK_)) + c);
            sm[(fstep*2 + kq)*32 + perm] = val;
        }
        load_quad(P0, vb, gb, bb, s + 8, col);   // for next iteration

        // ---- consume slots 4..7 (steps s+4..s+7) ----
        do_step(sm, 4, st, P1.v[0], P1.g[0], P1.b[0], ob + (size_t)(s+4)*(H_*DV_), rg, col);
        do_step(sm, 5, st, P1.v[1], P1.g[1], P1.b[1], ob + (size_t)(s+5)*(H_*DV_), rg, col);
        do_step(sm, 6, st, P1.v[2], P1.g[2], P1.b[2], ob + (size_t)(s+6)*(H_*DV_), rg, col);
        do_step(sm, 7, st, P1.v[3], P1.g[3], P1.b[3], ob + (size_t)(s+7)*(H_*DV_), rg, col);

        __syncthreads();   // slots 4..7 consumed

        // fill slots 4..7 <- steps s+12..s+15 (consumed in next iter,
        // RAW ordered by next iter's first barrier)
        {
            int fs = s + 12 + fstep;
            if (fs > S_ - 1) fs = S_ - 1;
            float4 val = __ldg((const float4*)(fsrc + (size_t)fs*(H_*DK_)) + c);
            sm[((4 + fstep)*2 + kq)*32 + perm] = val;
        }
    }
}

// ============================================================
extern "C" void kernel_launch(void* const* d_in, const int* in_sizes, int n_in,
                              void* d_out, int out_size)
{
    (void)in_sizes; (void)n_in; (void)out_size;
    const float* x   = (const float*)d_in[0];
    const float* q   = (const float*)d_in[1];
    const float* k   = (const float*)d_in[2];
    const float* v   = (const float*)d_in[3];
    const float* Wa  = (const float*)d_in[4];
    const float* Wb  = (const float*)d_in[5];
    const float* dtb = (const float*)d_in[6];
    const float* Al  = (const float*)d_in[7];
    float* out = (float*)d_out;

    gate_kernel<<<P_/GT_POS, 256>>>(x, Wa, Wb, dtb, Al);
    scan_kernel<<<B_*H_*4, 256>>>(q, k, v, out);
}

// round 13
// speedup vs baseline: 1.4108x; 1.0088x over previous
#include <cuda_runtime.h>

#define B_   4
#define S_   2048
#define H_   16
#define HID_ 2048
#define DK_  128
#define DV_  128
#define P_   (B_*S_)   // 8192 positions

// scratch (allowed: __device__ globals)
__device__ float g_decay[P_*H_];
__device__ float g_beta [P_*H_];

// ============================================================
// Kernel 1: gating GEMM  raw = x @ [Wa;Wb]^T  + epilogue
// ============================================================
#define GT_POS 64
#define GT_K   32

__global__ __launch_bounds__(256) void gate_kernel(
    const float* __restrict__ x,
    const float* __restrict__ Wa, const float* __restrict__ Wb,
    const float* __restrict__ dt_bias, const float* __restrict__ A_log)
{
    __shared__ float xs[GT_POS][GT_K+1];
    __shared__ float ws[32][GT_K+1];
    int t  = threadIdx.x;
    int p0 = blockIdx.x * GT_POS;
    int tx = t & 7;
    int ty = t >> 3;
    float acc[2][4] = {};

    for (int kc = 0; kc < HID_; kc += GT_K) {
        #pragma unroll
        for (int i = 0; i < (GT_POS*GT_K)/256; ++i) {
            int e = i*256 + t; int r = e >> 5, c = e & 31;
            xs[r][c] = x[(size_t)(p0 + r)*HID_ + kc + c];
        }
        #pragma unroll
        for (int i = 0; i < (32*GT_K)/256; ++i) {
            int e = i*256 + t; int f = e >> 5, c = e & 31;
            const float* wrow = (f < 16) ? (Wa + f*HID_) : (Wb + (f-16)*HID_);
            ws[f][c] = wrow[kc + c];
        }
        __syncthreads();
        #pragma unroll
        for (int k = 0; k < GT_K; ++k) {
            float xv0 = xs[2*ty  ][k];
            float xv1 = xs[2*ty+1][k];
            #pragma unroll
            for (int j = 0; j < 4; ++j) {
                float wv = ws[4*tx+j][k];
                acc[0][j] = fmaf(xv0, wv, acc[0][j]);
                acc[1][j] = fmaf(xv1, wv, acc[1][j]);
            }
        }
        __syncthreads();
    }

    #pragma unroll
    for (int i = 0; i < 2; ++i) {
        int p = p0 + 2*ty + i;
        #pragma unroll
        for (int j = 0; j < 4; ++j) {
            int f = 4*tx + j;
            float r = acc[i][j];
            if (f < 16) {
                float z  = r + __ldg(dt_bias + f);
                float sp = fmaxf(z, 0.0f) + log1pf(expf(-fabsf(z)));
                g_decay[p*H_ + f] = expf(-expf(__ldg(A_log + f)) * sp);
            } else {
                g_beta[p*H_ + (f-16)] = r;
            }
        }
    }
}

// ============================================================
// Kernel 2: delta-rule scan. 4 lanes per DV column.
// CTA = 128 thr = 4 warps x 8 cols; grid = 64 bh x 4 colcta = 256.
// Lane (co = lane>>2 owns col, sub = lane&3) owns rows
// {16t + 4*sub .. +3}, t = 0..7  (16 u64 of state).
// SMEM ring: 8 slots x {k,q} x 32 float4. Fill swizzle: chunk c
// stored at index (c&3)*8 + (((c>>2)+(c&3))&7); consumer LDS t at
// index sub*8 + ((t+sub)&7) returns rows 16t+4sub..+3, banks
// 4*((t+sub)&7) distinct across sub -> conflict-free, 8-way
// broadcast across co.
// Per step:
//   p = redux4( k . S[:,col] )      (hadd + xor1,2)
//   d = (v - g*p) * beta
//   S = g*S + k (x) d
//   o = redux4( q . S_new[:,col] )  (off recurrence path)
// ============================================================
typedef unsigned long long u64;

__device__ __forceinline__ u64 fma2(u64 a, u64 b, u64 c) {
    u64 d; asm("fma.rn.f32x2 %0, %1, %2, %3;" : "=l"(d) : "l"(a), "l"(b), "l"(c));
    return d;
}
__device__ __forceinline__ u64 mul2(u64 a, u64 b) {
    u64 d; asm("mul.rn.f32x2 %0, %1, %2;" : "=l"(d) : "l"(a), "l"(b));
    return d;
}
__device__ __forceinline__ u64 pack2(float x, float y) {
    u64 d; asm("mov.b64 %0, {%1, %2};" : "=l"(d)
               : "r"(__float_as_uint(x)), "r"(__float_as_uint(y)));
    return d;
}
__device__ __forceinline__ float hadd2(u64 a) {
    unsigned lo, hi;
    asm("mov.b64 {%0, %1}, %2;" : "=r"(lo), "=r"(hi) : "l"(a));
    return __uint_as_float(lo) + __uint_as_float(hi);
}

struct QuadPre {                 // prefetched v/g/beta for 4 steps
    float v[4], g[4], b[4];
};

__device__ __forceinline__ void load_quad(QuadPre& p,
    const float* vb, const float* gb, const float* bb, int s, int col)
{
    #pragma unroll
    for (int i = 0; i < 4; ++i) {
        int si = s + i; if (si > S_ - 1) si = S_ - 1;
        p.v[i] = __ldg(vb + (size_t)si * (H_*DK_) + col);
        p.g[i] = __ldg(gb + (size_t)si * H_);
        p.b[i] = __ldg(bb + (size_t)si * H_);
    }
}

// one scan step; slotbase = slot*64 (float4 units to k region)
__device__ __forceinline__ void do_step(const float4* sm, int slotbase,
                                        const int ofs[8], u64 st[16],
                                        float v, float g, float be,
                                        float* outp, int sub, int col)
{
    const unsigned FM = 0xffffffffu;
    const float4* kreg = sm + slotbase;
    const float4* qreg = sm + slotbase + 32;

    u64 k2[16];
    #pragma unroll
    for (int t = 0; t < 8; ++t) {
        ulonglong2 kk = *reinterpret_cast<const ulonglong2*>(kreg + ofs[t]);
        k2[2*t] = kk.x; k2[2*t+1] = kk.y;
    }

    // ---- p = k . S[:,col], 4-accumulator tree ----
    u64 pa = mul2(k2[0], st[0]);
    u64 pb = mul2(k2[1], st[1]);
    u64 pc = mul2(k2[2], st[2]);
    u64 pd = mul2(k2[3], st[3]);
    #pragma unroll
    for (int j = 4; j < 16; j += 4) {
        pa = fma2(k2[j+0], st[j+0], pa);
        pb = fma2(k2[j+1], st[j+1], pb);
        pc = fma2(k2[j+2], st[j+2], pc);
        pd = fma2(k2[j+3], st[j+3], pd);
    }
    float p = (hadd2(pa) + hadd2(pb)) + (hadd2(pc) + hadd2(pd));
    p += __shfl_xor_sync(FM, p, 1);
    p += __shfl_xor_sync(FM, p, 2);

    // ---- delta ----
    float d = fmaf(-g, p, v) * be;

    // ---- state update: S = g*S + k (x) d ----
    u64 gp = pack2(g, g), dp = pack2(d, d);
    #pragma unroll
    for (int j = 0; j < 16; ++j)
        st[j] = fma2(k2[j], dp, mul2(gp, st[j]));

    // ---- o = q . S_new[:,col] (off recurrence critical path) ----
    u64 q2[16];
    #pragma unroll
    for (int t = 0; t < 8; ++t) {
        ulonglong2 qq = *reinterpret_cast<const ulonglong2*>(qreg + ofs[t]);
        q2[2*t] = qq.x; q2[2*t+1] = qq.y;
    }
    u64 oa = mul2(q2[0], st[0]);
    u64 ob = mul2(q2[1], st[1]);
    u64 oc = mul2(q2[2], st[2]);
    u64 od = mul2(q2[3], st[3]);
    #pragma unroll
    for (int j = 4; j < 16; j += 4) {
        oa = fma2(q2[j+0], st[j+0], oa);
        ob = fma2(q2[j+1], st[j+1], ob);
        oc = fma2(q2[j+2], st[j+2], oc);
        od = fma2(q2[j+3], st[j+3], od);
    }
    float o = (hadd2(oa) + hadd2(ob)) + (hadd2(oc) + hadd2(od));
    o += __shfl_xor_sync(FM, o, 1);
    o += __shfl_xor_sync(FM, o, 2);

    if (sub == 0)
        outp[col] = o;
}

__global__ void __launch_bounds__(128, 2) scan_kernel(
    const float* __restrict__ q, const float* __restrict__ k,
    const float* __restrict__ v, float* __restrict__ out)
{
    // smem ring: 8 slots x {k,q} x 32 float4 (8 KB)
    __shared__ float4 sm[8*2*32];

    int bid    = blockIdx.x;         // 256 CTAs
    int colcta = bid & 3;            // 32-col slice
    int bh     = bid >> 2;
    int b      = bh >> 4, h = bh & 15;
    int tid    = threadIdx.x;
    int w      = tid >> 5;           // warp 0..3
    int lane   = tid & 31;
    int co     = lane >> 2;          // col owner 0..7
    int sub    = lane & 3;           // row slice
    int col    = colcta*32 + w*8 + co;

    size_t base = ((size_t)b * S_ * H_ + h) * DK_;
    const float* kb = k + base;
    const float* qb = q + base;
    const float* vb = v + base;
    float*       ob = out + base;
    const float* gb = g_decay + (size_t)b * S_ * H_ + h;
    const float* bb = g_beta  + (size_t)b * S_ * H_ + h;

    // consumer LDS offsets (per vector region, float4 units)
    int ofs[8];
    #pragma unroll
    for (int t = 0; t < 8; ++t)
        ofs[t] = sub*8 + ((t + sub) & 7);

    // fill params: warp w stages vector (w&1) of slots (w>>1)+{0,2,...}
    int fvec  = w & 1;               // 0 = k, 1 = q
    int fsoff = w >> 1;              // 0 or 1
    int fidx  = ((lane & 3) << 3) | ((((lane >> 2) + (lane & 3))) & 7);
    const float* fsrc = fvec ? qb : kb;

    // ---- pre-fill slots 0..7 = steps 0..7 (each warp: 4 slots) ----
    #pragma unroll
    for (int i = 0; i < 4; ++i) {
        int fs = fsoff + 2*i;        // slots {0,2,4,6} or {1,3,5,7}
        float4 val = __ldg((const float4*)(fsrc + (size_t)fs*(H_*DK_)) + lane);
        sm[(fs*2 + fvec)*32 + fidx] = val;
    }
    __syncthreads();

    u64 st[16];
    #pragma unroll
    for (int j = 0; j < 16; ++j) st[j] = 0ull;

    QuadPre P0, P1;
    load_quad(P0, vb, gb, bb, 0, col);

    for (int s = 0; s < S_; s += 8) {
        load_quad(P1, vb, gb, bb, s + 4, col);

        // ---- consume slots 0..3 (steps s..s+3) ----
        do_step(sm, 0*64, ofs, st, P0.v[0], P0.g[0], P0.b[0], ob + (size_t)(s  )*(H_*DV_), sub, col);
        do_step(sm, 1*64, ofs, st, P0.v[1], P0.g[1], P0.b[1], ob + (size_t)(s+1)*(H_*DV_), sub, col);
        do_step(sm, 2*64, ofs, st, P0.v[2], P0.g[2], P0.b[2], ob + (size_t)(s+2)*(H_*DV_), sub, col);
        do_step(sm, 3*64, ofs, st, P0.v[3], P0.g[3], P0.b[3], ob + (size_t)(s+3)*(H_*DV_), sub, col);

        __syncthreads();   // slots 0..3 consumed by all warps

        // fill slots 0..3 <- steps s+8..s+11 (warp w: slots fsoff, fsoff+2)
        {
            int s0 = s + 8 + fsoff;   if (s0 > S_ - 1) s0 = S_ - 1;
            int s1 = s + 10 + fsoff;  if (s1 > S_ - 1) s1 = S_ - 1;
            float4 v0 = __ldg((const float4*)(fsrc + (size_t)s0*(H_*DK_)) + lane);
            float4 v1 = __ldg((const float4*)(fsrc + (size_t)s1*(H_*DK_)) + lane);
            sm[((fsoff    )*2 + fvec)*32 + fidx] = v0;
            sm[((fsoff + 2)*2 + fvec)*32 + fidx] = v1;
        }
        load_quad(P0, vb, gb, bb, s + 8, col);   // for next iteration

        // ---- consume slots 4..7 (steps s+4..s+7) ----
        do_step(sm, 4*64, ofs, st, P1.v[0], P1.g[0], P1.b[0], ob + (size_t)(s+4)*(H_*DV_), sub, col);
        do_step(sm, 5*64, ofs, st, P1.v[1], P1.g[1], P1.b[1], ob + (size_t)(s+5)*(H_*DV_), sub, col);
        do_step(sm, 6*64, ofs, st, P1.v[2], P1.g[2], P1.b[2], ob + (size_t)(s+6)*(H_*DV_), sub, col);
        do_step(sm, 7*64, ofs, st, P1.v[3], P1.g[3], P1.b[3], ob + (size_t)(s+7)*(H_*DV_), sub, col);

        __syncthreads();   // slots 4..7 consumed

        // fill slots 4..7 <- steps s+12..s+15 (RAW ordered by next iter's
        // first barrier)
        {
            int s2 = s + 12 + fsoff;  if (s2 > S_ - 1) s2 = S_ - 1;
            int s3 = s + 14 + fsoff;  if (s3 > S_ - 1) s3 = S_ - 1;
            float4 v2 = __ldg((const float4*)(fsrc + (size_t)s2*(H_*DK_)) + lane);
            float4 v3 = __ldg((const float4*)(fsrc + (size_t)s3*(H_*DK_)) + lane);
            sm[((4 + fsoff)*2 + fvec)*32 + fidx] = v2;
            sm[((6 + fsoff)*2 + fvec)*32 + fidx] = v3;
        }
    }
}

// ============================================================
extern "C" void kernel_launch(void* const* d_in, const int* in_sizes, int n_in,
                              void* d_out, int out_size)
{
    (void)in_sizes; (void)n_in; (void)out_size;
    const float* x   = (const float*)d_in[0];
    const float* q   = (const float*)d_in[1];
    const float* k   = (const float*)d_in[2];
    const float* v   = (const float*)d_in[3];
    const float* Wa  = (const float*)d_in[4];
    const float* Wb  = (const float*)d_in[5];
    const float* dtb = (const float*)d_in[6];
    const float* Al  = (const float*)d_in[7];
    float* out = (float*)d_out;

    gate_kernel<<<P_/GT_POS, 256>>>(x, Wa, Wb, dtb, Al);
    scan_kernel<<<B_*H_*4, 128>>>(q, k, v, out);
}